// round 8
// baseline (speedup 1.0000x reference)
#include <cuda_runtime.h>
#include <cstdint>

#define NT    16384
#define DIM   2048
#define NE    64
#define TT    64
#define NCHK  32             // chunks of 4 ksteps (k64) -- FIX: was 16, dropped half of K
#define NKS   128            // k16 steps
#define LSTR  66
#define GAP_THRESH 1e-4f

// w fragment table: [s(128)][p(2)][h8(2)] blocks of 2560B = [t(32) stride 80B][r(2)*32B][J(8)*4B]
#define BLK_B   2560
#define KS_B    (4 * BLK_B)          // 10240 per kstep
#define CH_B    (4 * KS_B)           // 40960 per chunk (4 ksteps)
#define WF_FLOATS (128 * KS_B / 4)
#define STG_B   CH_B
#define SMEM_TOTAL (2 * STG_B)       // 81920

__device__ __align__(16) float g_wf[WF_FLOATS];   // 1.31 MB, L2-resident

__device__ __forceinline__ uint32_t smem_u32(const void* p) {
    uint32_t a;
    asm("{ .reg .u64 t; cvta.to.shared.u64 t, %1; cvt.u32.u64 %0, t; }" : "=r"(a) : "l"(p));
    return a;
}
__device__ __forceinline__ uint32_t tf32rn(float a) {
    return (__float_as_uint(a) + 0x1000u) & 0xFFFFE000u;
}
__device__ __forceinline__ void mma_tf32(float* c, const uint32_t* a,
                                         uint32_t b0, uint32_t b1) {
    asm volatile("mma.sync.aligned.m16n8k8.row.col.f32.tf32.tf32.f32 "
                 "{%0,%1,%2,%3}, {%4,%5,%6,%7}, {%8,%9}, {%0,%1,%2,%3};"
                 : "+f"(c[0]), "+f"(c[1]), "+f"(c[2]), "+f"(c[3])
                 : "r"(a[0]), "r"(a[1]), "r"(a[2]), "r"(a[3]), "r"(b0), "r"(b1));
}
#define CP16(sa, ga) \
    asm volatile("cp.async.ca.shared.global [%0], [%1], 16;" :: "r"(sa), "l"(ga))
#define CP_COMMIT() asm volatile("cp.async.commit_group;" ::: "memory")
#define CP_WAIT(n)  asm volatile("cp.async.wait_group %0;" :: "n"(n) : "memory")

// ---- prep: w -> tf32 h/m planes in fragment order ----
__global__ __launch_bounds__(256) void prep_wf(const float* __restrict__ w) {
    const int idx = blockIdx.x * 256 + threadIdx.x;     // 32768 = 64e * 512 k4
    const int e = idx >> 9, k4 = idx & 511;
    float4 v = *reinterpret_cast<const float4*>(w + (size_t)e * DIM + k4 * 4);
    const float vv[4] = {v.x, v.y, v.z, v.w};
#pragma unroll
    for (int q = 0; q < 4; q++) {
        const int k = k4 * 4 + q;
        const int s = k >> 4, h8 = (k >> 3) & 1, r = (k >> 2) & 1, tk = k & 3;
        const int J = e >> 3, tn = e & 7, t = tn * 4 + tk;
        const int base = (s * 4) * 640 + (h8)*640 + t * 20 + r * 8 + J;  // p=0
        uint32_t h = tf32rn(vv[q]);
        float mf = vv[q] - __uint_as_float(h);
        uint32_t m = tf32rn(mf);
        g_wf[base]             = __uint_as_float(h);
        g_wf[base + 2 * 640]   = __uint_as_float(m);     // p=1 block offset
    }
}

// ---- main ----
__global__ __launch_bounds__(256, 2)
void router_tf32(const float* __restrict__ x, const float* __restrict__ w,
                 float* __restrict__ out)
{
    extern __shared__ __align__(1024) char smem[];
    const uint32_t sb = smem_u32(smem);

    __shared__ int   s_cnt;
    __shared__ int   s_list[TT];
    __shared__ float s_part[4][64];
    __shared__ float s_lg[66];

    const int tid  = threadIdx.x;
    const int lane = tid & 31;
    const int wp   = tid >> 5;       // 0..7
    const int tg   = wp & 3;         // token group x16
    const int eh   = wp >> 2;        // expert half x32 (ntiles eh*4..+3)
    const int tok0 = blockIdx.x * TT;

    if (tid == 0) s_cnt = 0;

    // A gmem addressing: row = tg*16 + (lane>>2) (+8), k = (lane&3) + 4*kq + 16*g
    const float* xa = x + (size_t)(tok0 + tg * 16 + (lane >> 2)) * DIM + (lane & 3);

    float acc[4][4];
#pragma unroll
    for (int j = 0; j < 4; j++)
#pragma unroll
        for (int q = 0; q < 4; q++) acc[j][q] = 0.0f;

    // 4-deep A prefetch: pa[stage][kq*2+rh]
    float pa[4][8];
    auto loadA = [&](int g, int st) {
        const float* p = xa + 16 * g;
#pragma unroll
        for (int kq = 0; kq < 4; kq++) {
#pragma unroll
            for (int rh = 0; rh < 2; rh++)
                pa[st][kq * 2 + rh] = p[kq * 4 + rh * 8 * DIM];
        }
    };
#pragma unroll
    for (int g = 0; g < 4; g++) loadA(g, g);

    const char* wf = reinterpret_cast<const char*>(g_wf);
    auto issueW = [&](int ch, int buf) {
#pragma unroll
        for (int it = 0; it < 10; it++) {
            int i = tid + 256 * it;                     // 0..2559
            uint32_t sa = sb + (uint32_t)(buf * STG_B + i * 16);
            CP16(sa, wf + (size_t)ch * CH_B + i * 16);
        }
    };
    issueW(0, 0);
    CP_COMMIT();

    const uint32_t lane80 = (uint32_t)(lane * 80 + eh * 16);

    for (int ch = 0; ch < NCHK; ch++) {
        __syncthreads();                      // all warps done with old buffer
        if (ch + 1 < NCHK) { issueW(ch + 1, (ch + 1) & 1); CP_COMMIT(); CP_WAIT(1); }
        else               { CP_WAIT(0); }
        __syncthreads();                      // this chunk's data visible

        const uint32_t bufb = sb + (uint32_t)((ch & 1) * STG_B);
#pragma unroll
        for (int sl = 0; sl < 4; sl++) {
            const int g = ch * 4 + sl;
            const int st = g & 3;
            const uint32_t ksb = bufb + (uint32_t)(sl * KS_B) + lane80;

            // split A for both k8 halves
            uint32_t ah[2][4], am[2][4];
#pragma unroll
            for (int h8 = 0; h8 < 2; h8++)
#pragma unroll
                for (int i = 0; i < 4; i++) {
                    float a = pa[st][4 * h8 + i];
                    uint32_t h = tf32rn(a);
                    ah[h8][i] = h;
                    am[h8][i] = tf32rn(a - __uint_as_float(h));
                }
            if (g + 4 < NKS) loadA(g + 4, st);

#pragma unroll
            for (int h8 = 0; h8 < 2; h8++) {
                const uint32_t blkh = ksb + (uint32_t)(h8 * BLK_B);
                uint4 bh0 = *reinterpret_cast<const uint4*>(smem + (blkh - sb));
                uint4 bh1 = *reinterpret_cast<const uint4*>(smem + (blkh - sb) + 32);
                uint4 bm0 = *reinterpret_cast<const uint4*>(smem + (blkh - sb) + 2 * BLK_B);
                uint4 bm1 = *reinterpret_cast<const uint4*>(smem + (blkh - sb) + 2 * BLK_B + 32);
                const uint32_t* b0h = reinterpret_cast<const uint32_t*>(&bh0);
                const uint32_t* b1h = reinterpret_cast<const uint32_t*>(&bh1);
                const uint32_t* b0m = reinterpret_cast<const uint32_t*>(&bm0);
                const uint32_t* b1m = reinterpret_cast<const uint32_t*>(&bm1);
#pragma unroll
                for (int j = 0; j < 4; j++) {
                    mma_tf32(acc[j], ah[h8], b0h[j], b1h[j]);
                    mma_tf32(acc[j], ah[h8], b0m[j], b1m[j]);
                    mma_tf32(acc[j], am[h8], b0h[j], b1h[j]);
                }
            }
        }
    }

    // ---- logits -> smem ----
    __syncthreads();
    float* ls = reinterpret_cast<float*>(smem);
    {
        const int qrow = lane >> 2, qk = (lane & 3) * 2;
        const int r0 = tg * 16 + qrow, r1 = r0 + 8;
        const int e00 = eh * 32 + qk;
#pragma unroll
        for (int j = 0; j < 4; j++) {
            int e = e00 + 8 * j;
            *reinterpret_cast<float2*>(ls + r0 * LSTR + e) = make_float2(acc[j][0], acc[j][1]);
            *reinterpret_cast<float2*>(ls + r1 * LSTR + e) = make_float2(acc[j][2], acc[j][3]);
        }
    }
    __syncthreads();

    float* outp = out;
    float* outi = out + (size_t)NT * 8;
    float* outa = out + (size_t)NT * 16;

    const int tbase = wp * 8;
#pragma unroll 1
    for (int tt = 0; tt < 8; tt++) {
        const int tok = tbase + tt;
        float2 v = *reinterpret_cast<const float2*>(ls + tok * LSTR + 2 * lane);

        float m = fmaxf(v.x, v.y);
#pragma unroll
        for (int o = 16; o > 0; o >>= 1)
            m = fmaxf(m, __shfl_xor_sync(0xffffffffu, m, o));

        float e0 = expf(v.x - m);
        float e1 = expf(v.y - m);
        float ssum = e0 + e1;
#pragma unroll
        for (int o = 16; o > 0; o >>= 1)
            ssum += __shfl_xor_sync(0xffffffffu, ssum, o);

        float inv = 1.0f / ssum;
        float p0 = e0 * inv, p1 = e1 * inv;

        const int gtok = tok0 + tok;
        *reinterpret_cast<float2*>(outa + (size_t)gtok * 64 + 2 * lane)
            = make_float2(p0, p1);

        // top-9 on logits, min adjacent gap -> flag near-ties
        float c0 = v.x, c1 = v.y;
        int i0 = 2 * lane, i1 = 2 * lane + 1;
        float tv = 0.0f, tsum = 0.0f, prevv = 0.0f, mingap = 1e30f;
        int ti = 0;
#pragma unroll
        for (int r = 0; r < 9; r++) {
            float bv; int bi;
            if (c0 > c1 || (c0 == c1 && i0 < i1)) { bv = c0; bi = i0; }
            else                                  { bv = c1; bi = i1; }
#pragma unroll
            for (int o = 16; o > 0; o >>= 1) {
                float ov = __shfl_xor_sync(0xffffffffu, bv, o);
                int   oi = __shfl_xor_sync(0xffffffffu, bi, o);
                if (ov > bv || (ov == bv && oi < bi)) { bv = ov; bi = oi; }
            }
            if (r > 0) mingap = fminf(mingap, prevv - bv);
            prevv = bv;
            if (r < 8) {
                float bp = expf(bv - m) * inv;
                tsum += bp;
                if (lane == r) { tv = bp; ti = bi; }
                if (bi == i0)      c0 = -1e30f;
                else if (bi == i1) c1 = -1e30f;
            }
        }
        if (lane < 8) {
            outp[(size_t)gtok * 8 + lane] = tv / (tsum + 1e-9f);
            outi[(size_t)gtok * 8 + lane] = (float)ti;
        }
        if (lane == 0 && mingap < GAP_THRESH) {
            int pos = atomicAdd(&s_cnt, 1);
            s_list[pos] = gtok;
        }
    }

    // ---- inline exact fp32 fixup ----
    __syncthreads();
    const int nfix = s_cnt;
    for (int i = 0; i < nfix; i++) {
        const int tok = s_list[i];
        const int e = tid & 63, kp = tid >> 6;
        const float* xr = x + (size_t)tok * DIM + kp * 512;
        const float* wr = w + (size_t)e * DIM + kp * 512;
        float s = 0.0f;
#pragma unroll 4
        for (int k = 0; k < 512; k += 4) {
            float4 xv = *reinterpret_cast<const float4*>(xr + k);
            float4 wv = *reinterpret_cast<const float4*>(wr + k);
            s = fmaf(xv.x, wv.x, s);
            s = fmaf(xv.y, wv.y, s);
            s = fmaf(xv.z, wv.z, s);
            s = fmaf(xv.w, wv.w, s);
        }
        s_part[kp][e] = s;
        __syncthreads();
        if (tid < 64)
            s_lg[tid] = (s_part[0][tid] + s_part[1][tid]) + (s_part[2][tid] + s_part[3][tid]);
        __syncthreads();

        if (tid < 32) {
            float2 v = make_float2(s_lg[2 * lane], s_lg[2 * lane + 1]);

            float m = fmaxf(v.x, v.y);
#pragma unroll
            for (int o = 16; o > 0; o >>= 1)
                m = fmaxf(m, __shfl_xor_sync(0xffffffffu, m, o));

            float e0 = expf(v.x - m);
            float e1 = expf(v.y - m);
            float ssum = e0 + e1;
#pragma unroll
            for (int o = 16; o > 0; o >>= 1)
                ssum += __shfl_xor_sync(0xffffffffu, ssum, o);

            float inv = 1.0f / ssum;
            float p0 = e0 * inv, p1 = e1 * inv;

            *reinterpret_cast<float2*>(outa + (size_t)tok * 64 + 2 * lane)
                = make_float2(p0, p1);

            float c0 = p0, c1 = p1;
            int i0 = 2 * lane, i1 = 2 * lane + 1;
            float tv = 0.0f, tsum = 0.0f;
            int ti = 0;
#pragma unroll
            for (int r = 0; r < 8; r++) {
                float bv; int bi;
                if (c0 > c1 || (c0 == c1 && i0 < i1)) { bv = c0; bi = i0; }
                else                                  { bv = c1; bi = i1; }
#pragma unroll
                for (int o = 16; o > 0; o >>= 1) {
                    float ov = __shfl_xor_sync(0xffffffffu, bv, o);
                    int   oi = __shfl_xor_sync(0xffffffffu, bi, o);
                    if (ov > bv || (ov == bv && oi < bi)) { bv = ov; bi = oi; }
                }
                tsum += bv;
                if (lane == r) { tv = bv; ti = bi; }
                if (bi == i0)      c0 = -1.0f;
                else if (bi == i1) c1 = -1.0f;
            }
            if (lane < 8) {
                outp[(size_t)tok * 8 + lane] = tv / (tsum + 1e-9f);
                outi[(size_t)tok * 8 + lane] = (float)ti;
            }
        }
        __syncthreads();
    }
}

extern "C" void kernel_launch(void* const* d_in, const int* in_sizes, int n_in,
                              void* d_out, int out_size)
{
    (void)in_sizes; (void)n_in; (void)out_size;
    const float* x = (const float*)d_in[0];
    const float* w = (const float*)d_in[1];
    cudaFuncSetAttribute(router_tf32, cudaFuncAttributeMaxDynamicSharedMemorySize,
                         SMEM_TOTAL);
    prep_wf<<<128, 256>>>(w);
    router_tf32<<<NT / TT, 256, SMEM_TOTAL>>>(x, w, (float*)d_out);
}

// round 9
// speedup vs baseline: 1.3818x; 1.3818x over previous
#include <cuda_runtime.h>
#include <cuda_fp16.h>
#include <cstdint>

#define NT    16384
#define DIM   2048
#define NE    64
#define TT    64
#define KCH   64
#define NCHK  32
#define LSTR  66
#define GAP_THRESH 1e-4f

// dynamic smem: x16 planes 2 bufs @ [h|m][64 rows x 128B], then w16 same
#define XREG  0
#define WREG  32768
#define BUFB  16384
#define PLB   8192
#define SMEM_TOTAL 65536

// w fragment planes, chunk-ordered, pre-swizzled: [ch][h|m][e(64) x 128B]
__device__ __align__(16) unsigned char g_w[NCHK * BUFB];   // 512 KB

__device__ __forceinline__ uint32_t smem_u32(const void* p) {
    uint32_t a;
    asm("{ .reg .u64 t; cvta.to.shared.u64 t, %1; cvt.u32.u64 %0, t; }" : "=r"(a) : "l"(p));
    return a;
}
__device__ __forceinline__ void split2(float a, float b, uint32_t& h, uint32_t& m) {
    __half2 hh = __floats2half2_rn(a, b);
    float2 hf = __half22float2(hh);
    __half2 mm = __floats2half2_rn(a - hf.x, b - hf.y);
    h = *reinterpret_cast<uint32_t*>(&hh);
    m = *reinterpret_cast<uint32_t*>(&mm);
}
__device__ __forceinline__ void ldm4(uint32_t addr, uint32_t& r0, uint32_t& r1,
                                     uint32_t& r2, uint32_t& r3) {
    asm volatile("ldmatrix.sync.aligned.m8n8.x4.shared.b16 {%0,%1,%2,%3}, [%4];"
                 : "=r"(r0), "=r"(r1), "=r"(r2), "=r"(r3) : "r"(addr));
}
__device__ __forceinline__ void mma16816(float* c, const uint32_t* a,
                                         uint32_t b0, uint32_t b1) {
    asm volatile("mma.sync.aligned.m16n8k16.row.col.f32.f16.f16.f32 "
                 "{%0,%1,%2,%3}, {%4,%5,%6,%7}, {%8,%9}, {%0,%1,%2,%3};"
                 : "+f"(c[0]), "+f"(c[1]), "+f"(c[2]), "+f"(c[3])
                 : "r"(a[0]), "r"(a[1]), "r"(a[2]), "r"(a[3]), "r"(b0), "r"(b1));
}
#define SW128(o) ((o) ^ (((o) >> 3) & 0x70u))
#define CP16(sa, ga) \
    asm volatile("cp.async.ca.shared.global [%0], [%1], 16;" :: "r"(sa), "l"(ga))
#define CP_COMMIT() asm volatile("cp.async.commit_group;" ::: "memory")
#define CP_WAIT(n)  asm volatile("cp.async.wait_group %0;" :: "n"(n) : "memory")

// ---- prep: w (x256) -> fp16 h/m planes, chunk-ordered + pre-swizzled ----
__global__ __launch_bounds__(256) void prep_wf(const float* __restrict__ w) {
    const int idx = blockIdx.x * 256 + threadIdx.x;     // 16384
    const int e = idx >> 8;
    const int k = (idx & 255) * 8;
    float4 v0 = *reinterpret_cast<const float4*>(w + (size_t)e * DIM + k);
    float4 v1 = *reinterpret_cast<const float4*>(w + (size_t)e * DIM + k + 4);
    uint32_t h[4], m[4];
    split2(v0.x * 256.0f, v0.y * 256.0f, h[0], m[0]);
    split2(v0.z * 256.0f, v0.w * 256.0f, h[1], m[1]);
    split2(v1.x * 256.0f, v1.y * 256.0f, h[2], m[2]);
    split2(v1.z * 256.0f, v1.w * 256.0f, h[3], m[3]);
    const int ch = k >> 6, kc = k & 63;
    const uint32_t off = SW128((uint32_t)(e * 128 + kc * 2));
    *reinterpret_cast<uint4*>(g_w + (size_t)ch * BUFB + off)       = make_uint4(h[0], h[1], h[2], h[3]);
    *reinterpret_cast<uint4*>(g_w + (size_t)ch * BUFB + PLB + off) = make_uint4(m[0], m[1], m[2], m[3]);
}

// ---- main ----
__global__ __launch_bounds__(256, 2)
void router_hmma(const float* __restrict__ x, const float* __restrict__ w,
                 float* __restrict__ out)
{
    extern __shared__ __align__(1024) char smem[];
    const uint32_t sb = smem_u32(smem);

    __shared__ int   s_cnt;
    __shared__ int   s_list[TT];
    __shared__ float s_part[4][64];
    __shared__ float s_lg[66];

    const int tid  = threadIdx.x;
    const int lane = tid & 31;
    const int wp   = tid >> 5;       // 0..7
    const int tg   = wp & 3;         // token group x16
    const int eh   = wp >> 2;        // expert half x32
    const int tok0 = blockIdx.x * TT;

    if (tid == 0) s_cnt = 0;

    // x loader: row = tid>>2, cols (tid&3)*16 + 0..15 (coalesced LDG.128 x4)
    const int xrow = tid >> 2, xcq = tid & 3;
    const float* xg = x + (size_t)(tok0 + xrow) * DIM + xcq * 16;
    const uint32_t st0 = SW128((uint32_t)(xrow * 128 + xcq * 32));
    const uint32_t st1 = SW128((uint32_t)(xrow * 128 + xcq * 32 + 16));

    float4 rx[4];
    auto loadX = [&](int ch) {
#pragma unroll
        for (int i = 0; i < 4; i++)
            rx[i] = *reinterpret_cast<const float4*>(xg + ch * KCH + i * 4);
    };

    const unsigned char* wsrc = g_w;
    auto issueW = [&](int ch, int b) {
#pragma unroll
        for (int it = 0; it < 4; it++) {
            int i = tid + 256 * it;        // 0..1023 (x16B = 16384B)
            CP16(sb + WREG + b * BUFB + i * 16, wsrc + (size_t)ch * BUFB + i * 16);
        }
    };

    // ldmatrix lane addressing (round-5 proven constants)
    const int l7 = lane & 7, gA = (lane >> 3) & 1, gB = lane >> 4;
    const uint32_t aRow  = (uint32_t)((tg * 16 + l7 + gA * 8) * 128);
    const uint32_t bRow0 = (uint32_t)((eh * 32 + l7 + gB * 8) * 128);
    const uint32_t bRow1 = bRow0 + 16 * 128;

    float acc[4][4];
#pragma unroll
    for (int j = 0; j < 4; j++)
#pragma unroll
        for (int q = 0; q < 4; q++) acc[j][q] = 0.0f;

    loadX(0);
    issueW(0, 0);
    CP_COMMIT();

    for (int ch = 0; ch < NCHK; ch++) {
        const int b = ch & 1;
        // 1) convert rx -> x16 planes (buf b)
        {
            uint32_t h[8], m[8];
#pragma unroll
            for (int i = 0; i < 4; i++) {
                split2(rx[i].x, rx[i].y, h[2 * i],     m[2 * i]);
                split2(rx[i].z, rx[i].w, h[2 * i + 1], m[2 * i + 1]);
            }
            char* xb = smem + XREG + b * BUFB;
            *reinterpret_cast<uint4*>(xb + st0)       = make_uint4(h[0], h[1], h[2], h[3]);
            *reinterpret_cast<uint4*>(xb + st1)       = make_uint4(h[4], h[5], h[6], h[7]);
            *reinterpret_cast<uint4*>(xb + PLB + st0) = make_uint4(m[0], m[1], m[2], m[3]);
            *reinterpret_cast<uint4*>(xb + PLB + st1) = make_uint4(m[4], m[5], m[6], m[7]);
        }
        // 2) wait this chunk's w
        CP_WAIT(0);
        // 3) one sync: x16/w16 visible; all warps done with other buffers
        __syncthreads();
        // 4) prefetch next chunk (after sync -> no cross-warp hazard)
        if (ch + 1 < NCHK) {
            issueW(ch + 1, b ^ 1);
            CP_COMMIT();
            loadX(ch + 1);
        }
        // 5) compute 4 ksteps
        const uint32_t xh = sb + XREG + (uint32_t)(b * BUFB) + aRow;
        const uint32_t wh0 = sb + WREG + (uint32_t)(b * BUFB) + bRow0;
        const uint32_t wh1 = sb + WREG + (uint32_t)(b * BUFB) + bRow1;
#pragma unroll
        for (int s = 0; s < 4; s++) {
            const uint32_t csA = (uint32_t)(((2 * s + gB) ^ l7) << 4);
            const uint32_t csB = (uint32_t)(((2 * s + gA) ^ l7) << 4);
            uint32_t ah[4], am[4], bh[8], bm[8];
            ldm4(xh + csA, ah[0], ah[1], ah[2], ah[3]);
            ldm4(xh + PLB + csA, am[0], am[1], am[2], am[3]);
            ldm4(wh0 + csB, bh[0], bh[1], bh[2], bh[3]);
            ldm4(wh1 + csB, bh[4], bh[5], bh[6], bh[7]);
#pragma unroll
            for (int j = 0; j < 4; j++) mma16816(acc[j], ah, bh[2 * j], bh[2 * j + 1]);
#pragma unroll
            for (int j = 0; j < 4; j++) mma16816(acc[j], am, bh[2 * j], bh[2 * j + 1]);
            ldm4(wh0 + PLB + csB, bm[0], bm[1], bm[2], bm[3]);
            ldm4(wh1 + PLB + csB, bm[4], bm[5], bm[6], bm[7]);
#pragma unroll
            for (int j = 0; j < 4; j++) mma16816(acc[j], ah, bm[2 * j], bm[2 * j + 1]);
        }
        __syncthreads();   // compute done before next chunk's STS overwrites buffers
    }

    // ---- logits -> smem (undo x256 w scale) ----
    float* ls = reinterpret_cast<float*>(smem);
    {
        const int qrow = lane >> 2, qk = (lane & 3) * 2;
        const int r0 = tg * 16 + qrow, r1 = r0 + 8;
        const int e00 = eh * 32 + qk;
#pragma unroll
        for (int j = 0; j < 4; j++) {
            int e = e00 + 8 * j;
            *reinterpret_cast<float2*>(ls + r0 * LSTR + e) =
                make_float2(acc[j][0] * 0.00390625f, acc[j][1] * 0.00390625f);
            *reinterpret_cast<float2*>(ls + r1 * LSTR + e) =
                make_float2(acc[j][2] * 0.00390625f, acc[j][3] * 0.00390625f);
        }
    }
    __syncthreads();

    float* outp = out;
    float* outi = out + (size_t)NT * 8;
    float* outa = out + (size_t)NT * 16;

    const int tbase = wp * 8;
#pragma unroll 1
    for (int tt = 0; tt < 8; tt++) {
        const int tok = tbase + tt;
        float2 v = *reinterpret_cast<const float2*>(ls + tok * LSTR + 2 * lane);

        float m = fmaxf(v.x, v.y);
#pragma unroll
        for (int o = 16; o > 0; o >>= 1)
            m = fmaxf(m, __shfl_xor_sync(0xffffffffu, m, o));

        float e0 = expf(v.x - m);
        float e1 = expf(v.y - m);
        float ssum = e0 + e1;
#pragma unroll
        for (int o = 16; o > 0; o >>= 1)
            ssum += __shfl_xor_sync(0xffffffffu, ssum, o);

        float inv = 1.0f / ssum;
        float p0 = e0 * inv, p1 = e1 * inv;

        const int gtok = tok0 + tok;
        *reinterpret_cast<float2*>(outa + (size_t)gtok * 64 + 2 * lane)
            = make_float2(p0, p1);

        // top-9 on logits, min adjacent gap -> flag near-ties
        float c0 = v.x, c1 = v.y;
        int i0 = 2 * lane, i1 = 2 * lane + 1;
        float tv = 0.0f, tsum = 0.0f, prevv = 0.0f, mingap = 1e30f;
        int ti = 0;
#pragma unroll
        for (int r = 0; r < 9; r++) {
            float bv; int bi;
            if (c0 > c1 || (c0 == c1 && i0 < i1)) { bv = c0; bi = i0; }
            else                                  { bv = c1; bi = i1; }
#pragma unroll
            for (int o = 16; o > 0; o >>= 1) {
                float ov = __shfl_xor_sync(0xffffffffu, bv, o);
                int   oi = __shfl_xor_sync(0xffffffffu, bi, o);
                if (ov > bv || (ov == bv && oi < bi)) { bv = ov; bi = oi; }
            }
            if (r > 0) mingap = fminf(mingap, prevv - bv);
            prevv = bv;
            if (r < 8) {
                float bp = expf(bv - m) * inv;
                tsum += bp;
                if (lane == r) { tv = bp; ti = bi; }
                if (bi == i0)      c0 = -1e30f;
                else if (bi == i1) c1 = -1e30f;
            }
        }
        if (lane < 8) {
            outp[(size_t)gtok * 8 + lane] = tv / (tsum + 1e-9f);
            outi[(size_t)gtok * 8 + lane] = (float)ti;
        }
        if (lane == 0 && mingap < GAP_THRESH) {
            int pos = atomicAdd(&s_cnt, 1);
            s_list[pos] = gtok;
        }
    }

    // ---- inline exact fp32 fixup ----
    __syncthreads();
    const int nfix = s_cnt;
    for (int i = 0; i < nfix; i++) {
        const int tok = s_list[i];
        const int e = tid & 63, kp = tid >> 6;
        const float* xr = x + (size_t)tok * DIM + kp * 512;
        const float* wr = w + (size_t)e * DIM + kp * 512;
        float s = 0.0f;
#pragma unroll 4
        for (int k = 0; k < 512; k += 4) {
            float4 xv = *reinterpret_cast<const float4*>(xr + k);
            float4 wv = *reinterpret_cast<const float4*>(wr + k);
            s = fmaf(xv.x, wv.x, s);
            s = fmaf(xv.y, wv.y, s);
            s = fmaf(xv.z, wv.z, s);
            s = fmaf(xv.w, wv.w, s);
        }
        s_part[kp][e] = s;
        __syncthreads();
        if (tid < 64)
            s_lg[tid] = (s_part[0][tid] + s_part[1][tid]) + (s_part[2][tid] + s_part[3][tid]);
        __syncthreads();

        if (tid < 32) {
            float2 v = make_float2(s_lg[2 * lane], s_lg[2 * lane + 1]);

            float m = fmaxf(v.x, v.y);
#pragma unroll
            for (int o = 16; o > 0; o >>= 1)
                m = fmaxf(m, __shfl_xor_sync(0xffffffffu, m, o));

            float e0 = expf(v.x - m);
            float e1 = expf(v.y - m);
            float ssum = e0 + e1;
#pragma unroll
            for (int o = 16; o > 0; o >>= 1)
                ssum += __shfl_xor_sync(0xffffffffu, ssum, o);

            float inv = 1.0f / ssum;
            float p0 = e0 * inv, p1 = e1 * inv;

            *reinterpret_cast<float2*>(outa + (size_t)tok * 64 + 2 * lane)
                = make_float2(p0, p1);

            float c0 = p0, c1 = p1;
            int i0 = 2 * lane, i1 = 2 * lane + 1;
            float tv = 0.0f, tsum = 0.0f;
            int ti = 0;
#pragma unroll
            for (int r = 0; r < 8; r++) {
                float bv; int bi;
                if (c0 > c1 || (c0 == c1 && i0 < i1)) { bv = c0; bi = i0; }
                else                                  { bv = c1; bi = i1; }
#pragma unroll
                for (int o = 16; o > 0; o >>= 1) {
                    float ov = __shfl_xor_sync(0xffffffffu, bv, o);
                    int   oi = __shfl_xor_sync(0xffffffffu, bi, o);
                    if (ov > bv || (ov == bv && oi < bi)) { bv = ov; bi = oi; }
                }
                tsum += bv;
                if (lane == r) { tv = bv; ti = bi; }
                if (bi == i0)      c0 = -1.0f;
                else if (bi == i1) c1 = -1.0f;
            }
            if (lane < 8) {
                outp[(size_t)tok * 8 + lane] = tv / (tsum + 1e-9f);
                outi[(size_t)tok * 8 + lane] = (float)ti;
            }
        }
        __syncthreads();
    }
}

extern "C" void kernel_launch(void* const* d_in, const int* in_sizes, int n_in,
                              void* d_out, int out_size)
{
    (void)in_sizes; (void)n_in; (void)out_size;
    const float* x = (const float*)d_in[0];
    const float* w = (const float*)d_in[1];
    cudaFuncSetAttribute(router_hmma, cudaFuncAttributeMaxDynamicSharedMemorySize,
                         SMEM_TOTAL);
    prep_wf<<<64, 256>>>(w);
    router_hmma<<<NT / TT, 256, SMEM_TOTAL>>>(x, w, (float*)d_out);
}